// round 4
// baseline (speedup 1.0000x reference)
#include <cuda_runtime.h>
#include <math.h>

#define N_NODES 102400
#define N_EDGES 1638400
#define IN_DIM  16
#define GNN_H   64
#define RNN_H   128
#define OUT_DIM 7
#define SEQ     50
#define BATCH   (N_NODES / SEQ)   // 2048
#define G4H     (4 * RNN_H)       // 512

// ---------------- scratch (device globals; no allocation allowed) ----------
__device__ int   g_is64;
__device__ int   g_ei[2 * N_EDGES];              // normalized int32 edge index
__device__ float g_deg[N_NODES];
__device__ float g_dinv[N_NODES];
__device__ float g_h1[N_NODES * GNN_H];
__device__ float g_a1[N_NODES * GNN_H];
__device__ float g_h2[N_NODES * GNN_H];
__device__ float g_a2[N_NODES * GNN_H];
__device__ float g_G[(size_t)N_NODES * G4H];     // gate precompute, reused per layer
__device__ float g_Y[(size_t)N_NODES * RNN_H];   // layer-0 LSTM outputs over time
__device__ float g_hst[BATCH * RNN_H];
__device__ float g_cst[BATCH * RNN_H];
__device__ float g_gates[BATCH * G4H];

// ---------------- edge-index dtype normalization ----------------------------
// If the raw buffer really is int64, all sampled values lie in [0, N_NODES).
// If it is int32, an int64 view fuses index pairs into huge values -> detect.
__global__ void k_detect(const void* __restrict__ ei) {
    const long long* p = (const long long*)ei;
    // sample 256 spread-out entries of the int64 view of the first half
    long long v = p[(size_t)threadIdx.x * (N_EDGES / 256)];
    int bad = (v < 0 || v >= N_NODES) ? 1 : 0;
    int any = __syncthreads_or(bad);
    if (threadIdx.x == 0) g_is64 = !any;
}

__global__ void k_convert(const void* __restrict__ ei) {
    int i = blockIdx.x * 256 + threadIdx.x;   // [0, 2*N_EDGES)
    int v;
    if (g_is64) v = (int)((const long long*)ei)[i];
    else        v = ((const int*)ei)[i];
    g_ei[i] = v;
}

// ---------------- GCN kernels ----------------------------------------------

__global__ void k_degree() {
    int e = blockIdx.x * 256 + threadIdx.x;
    atomicAdd(&g_deg[g_ei[N_EDGES + e]], 1.0f);
}

__global__ void k_dinv() {
    int i = blockIdx.x * 256 + threadIdx.x;
    float dg = g_deg[i];
    g_dinv[i] = rsqrtf(dg + 1.0f);   // +1 for self loop
}

// h = A[N_NODES, K] @ W[K, 64]; one thread per node row, W in smem
template <int K>
__global__ void __launch_bounds__(128) mm_nn64(const float* __restrict__ A,
                                               const float* __restrict__ W,
                                               float* __restrict__ C) {
    __shared__ float Ws[K][GNN_H];
    int tid = threadIdx.x;
    for (int i = tid; i < K * GNN_H / 4; i += 128)
        ((float4*)Ws)[i] = ((const float4*)W)[i];
    __syncthreads();

    size_t row = (size_t)blockIdx.x * 128 + tid;
    const float* arow = A + row * K;
    float acc[GNN_H];
#pragma unroll
    for (int j = 0; j < GNN_H; j++) acc[j] = 0.f;

    for (int k = 0; k < K; k++) {
        float a = __ldg(&arow[k]);
#pragma unroll
        for (int j = 0; j < GNN_H; j += 4) {
            float4 w = *(const float4*)&Ws[k][j];
            acc[j + 0] += a * w.x;
            acc[j + 1] += a * w.y;
            acc[j + 2] += a * w.z;
            acc[j + 3] += a * w.w;
        }
    }
    float* o = C + row * GNN_H;
#pragma unroll
    for (int j = 0; j < GNN_H; j += 4) {
        float4 v = make_float4(acc[j], acc[j + 1], acc[j + 2], acc[j + 3]);
        *(float4*)&o[j] = v;
    }
}

// edge scatter: out[dst] += h[src] * dinv[src] * dinv[dst]; 16 threads/edge
__global__ void k_scatter(const float* __restrict__ h,
                          float* __restrict__ out) {
    unsigned tid = blockIdx.x * 256 + threadIdx.x;
    unsigned e = tid >> 4;
    unsigned q = tid & 15;
    int s = g_ei[e];
    int d = g_ei[N_EDGES + e];
    float norm = g_dinv[s] * g_dinv[d];
    float4 v = *(const float4*)&h[(size_t)s * GNN_H + q * 4];
    float* o = &out[(size_t)d * GNN_H + q * 4];
    atomicAdd(o + 0, v.x * norm);
    atomicAdd(o + 1, v.y * norm);
    atomicAdd(o + 2, v.z * norm);
    atomicAdd(o + 3, v.w * norm);
}

// a = relu(a + h * dinv^2 + b)   (self-loop message + bias + relu)
__global__ void k_finalize(float* __restrict__ a, const float* __restrict__ h,
                           const float* __restrict__ b) {
    int tid = blockIdx.x * 256 + threadIdx.x;
    int n = tid >> 6, j = tid & 63;
    float di = g_dinv[n];
    float v = a[tid] + h[tid] * di * di + b[j];
    a[tid] = v > 0.f ? v : 0.f;
}

// ---------------- generic C = A[M,K] @ B[N,K]^T tiled SGEMM ----------------
// epilogue: + bias1[c] + bias2[c] + addm[r*addStride + c] (each nullable)
template <int BM, int BN, int TM, int TN>
__global__ void __launch_bounds__((BM / TM) * (BN / TN))
gemm_nt(const float* __restrict__ A, const float* __restrict__ B,
        float* __restrict__ C, int M, int N, int K,
        const float* __restrict__ bias1, const float* __restrict__ bias2,
        const float* __restrict__ addm, int addStride) {
    constexpr int BK = 16;
    constexpr int LDS = BK + 4;  // 20 floats => 80B rows, float4-aligned
    constexpr int NT = (BM / TM) * (BN / TN);
    __shared__ float As[BM * LDS];
    __shared__ float Bs[BN * LDS];

    int tid = threadIdx.x;
    constexpr int TCN = BN / TN;
    int tc = tid % TCN;
    int tr = tid / TCN;
    size_t brow = (size_t)blockIdx.x * BM;
    size_t bcol = (size_t)blockIdx.y * BN;

    float acc[TM][TN];
#pragma unroll
    for (int i = 0; i < TM; i++)
#pragma unroll
        for (int j = 0; j < TN; j++) acc[i][j] = 0.f;

    const float* Ab = A + brow * K;
    const float* Bb = B + bcol * K;

    for (int kt = 0; kt < K; kt += BK) {
#pragma unroll
        for (int i = tid; i < BM * 4; i += NT) {
            int r = i >> 2, v = i & 3;
            *(float4*)&As[r * LDS + v * 4] =
                *(const float4*)&Ab[(size_t)r * K + kt + v * 4];
        }
#pragma unroll
        for (int i = tid; i < BN * 4; i += NT) {
            int r = i >> 2, v = i & 3;
            *(float4*)&Bs[r * LDS + v * 4] =
                *(const float4*)&Bb[(size_t)r * K + kt + v * 4];
        }
        __syncthreads();
#pragma unroll
        for (int k = 0; k < BK; k += 4) {
            float4 af[TM], bf[TN];
#pragma unroll
            for (int i = 0; i < TM; i++)
                af[i] = *(float4*)&As[(tr * TM + i) * LDS + k];
#pragma unroll
            for (int j = 0; j < TN; j++)
                bf[j] = *(float4*)&Bs[(tc * TN + j) * LDS + k];
#pragma unroll
            for (int i = 0; i < TM; i++)
#pragma unroll
                for (int j = 0; j < TN; j++)
                    acc[i][j] += af[i].x * bf[j].x + af[i].y * bf[j].y +
                                 af[i].z * bf[j].z + af[i].w * bf[j].w;
        }
        __syncthreads();
    }

#pragma unroll
    for (int i = 0; i < TM; i++) {
        size_t r = brow + tr * TM + i;
#pragma unroll
        for (int j = 0; j < TN; j++) {
            size_t c = bcol + tc * TN + j;
            float v = acc[i][j];
            if (bias1) v += bias1[c];
            if (bias2) v += bias2[c];
            if (addm)  v += addm[r * (size_t)addStride + c];
            C[r * N + c] = v;
        }
    }
}

// ---------------- LSTM pointwise cell ---------------------------------------
__global__ void lstm_pw(const float* __restrict__ gates,
                        float* __restrict__ h, float* __restrict__ c,
                        float* __restrict__ Y, int t) {
    int tid = blockIdx.x * 256 + threadIdx.x;
    int b = tid >> 7, j = tid & 127;
    const float* g = gates + (size_t)b * G4H;
    float gi = g[j], gf = g[j + 128], gg = g[j + 256], go = g[j + 384];
    float si = 1.f / (1.f + expf(-gi));
    float sf = 1.f / (1.f + expf(-gf));
    float tg = tanhf(gg);
    float so = 1.f / (1.f + expf(-go));
    float cn = sf * c[tid] + si * tg;
    float hn = so * tanhf(cn);
    c[tid] = cn;
    h[tid] = hn;
    if (Y) Y[((size_t)b * SEQ + t) * RNN_H + j] = hn;
}

// ---------------- FC head ----------------------------------------------------
__global__ void __launch_bounds__(256) k_fc(const float* __restrict__ h,
                                            const float* __restrict__ fcw,
                                            const float* __restrict__ fcb,
                                            float* __restrict__ out) {
    __shared__ float Ws[RNN_H * OUT_DIM];
    int tid = threadIdx.x;
    for (int i = tid; i < RNN_H * OUT_DIM; i += 256) Ws[i] = fcw[i];
    __syncthreads();

    int g = blockIdx.x * 256 + tid;
    int b = g / OUT_DIM, o = g % OUT_DIM;
    if (b >= BATCH) return;
    const float* hr = h + (size_t)b * RNN_H;
    float acc = fcb[o];
#pragma unroll 8
    for (int k = 0; k < RNN_H; k++) acc += hr[k] * Ws[k * OUT_DIM + o];
    out[g] = acc;
}

// ---------------- host orchestration ----------------------------------------
extern "C" void kernel_launch(void* const* d_in, const int* in_sizes, int n_in,
                              void* d_out, int out_size) {
    // seq_len scalar may or may not be present at index 2
    int base = (in_sizes[2] == 1) ? 3 : 2;
    const float* x    = (const float*)d_in[0];
    const void*  ei   = d_in[1];
    const float* w1   = (const float*)d_in[base + 0];
    const float* b1   = (const float*)d_in[base + 1];
    const float* w2   = (const float*)d_in[base + 2];
    const float* b2   = (const float*)d_in[base + 3];
    const float* wih0 = (const float*)d_in[base + 4];
    const float* whh0 = (const float*)d_in[base + 5];
    const float* bih0 = (const float*)d_in[base + 6];
    const float* bhh0 = (const float*)d_in[base + 7];
    const float* wih1 = (const float*)d_in[base + 8];
    const float* whh1 = (const float*)d_in[base + 9];
    const float* bih1 = (const float*)d_in[base + 10];
    const float* bhh1 = (const float*)d_in[base + 11];
    const float* fcw  = (const float*)d_in[base + 12];
    const float* fcb  = (const float*)d_in[base + 13];
    float* out = (float*)d_out;

    float *pdeg, *ph1, *pa1, *ph2, *pa2, *pG, *pY, *ph, *pc, *pg;
    cudaGetSymbolAddress((void**)&pdeg, g_deg);
    cudaGetSymbolAddress((void**)&ph1, g_h1);
    cudaGetSymbolAddress((void**)&pa1, g_a1);
    cudaGetSymbolAddress((void**)&ph2, g_h2);
    cudaGetSymbolAddress((void**)&pa2, g_a2);
    cudaGetSymbolAddress((void**)&pG,  g_G);
    cudaGetSymbolAddress((void**)&pY,  g_Y);
    cudaGetSymbolAddress((void**)&ph,  g_hst);
    cudaGetSymbolAddress((void**)&pc,  g_cst);
    cudaGetSymbolAddress((void**)&pg,  g_gates);

    cudaMemsetAsync(pdeg, 0, N_NODES * sizeof(float), 0);
    cudaMemsetAsync(pa1, 0, (size_t)N_NODES * GNN_H * sizeof(float), 0);
    cudaMemsetAsync(pa2, 0, (size_t)N_NODES * GNN_H * sizeof(float), 0);
    cudaMemsetAsync(ph, 0, BATCH * RNN_H * sizeof(float), 0);
    cudaMemsetAsync(pc, 0, BATCH * RNN_H * sizeof(float), 0);

    // --- normalize edge_index dtype (int32 vs int64) on device
    k_detect<<<1, 256>>>(ei);
    k_convert<<<(2 * N_EDGES) / 256, 256>>>(ei);

    // --- GCN layer 1
    k_degree<<<N_EDGES / 256, 256>>>();
    k_dinv<<<N_NODES / 256, 256>>>();
    mm_nn64<IN_DIM><<<N_NODES / 128, 128>>>(x, w1, ph1);
    k_scatter<<<(N_EDGES * 16) / 256, 256>>>(ph1, pa1);
    k_finalize<<<(N_NODES * GNN_H) / 256, 256>>>(pa1, ph1, b1);

    // --- GCN layer 2
    mm_nn64<GNN_H><<<N_NODES / 128, 128>>>(pa1, w2, ph2);
    k_scatter<<<(N_EDGES * 16) / 256, 256>>>(ph2, pa2);
    k_finalize<<<(N_NODES * GNN_H) / 256, 256>>>(pa2, ph2, b2);

    // --- LSTM layer 0: gate precompute then 50 recurrent steps
    dim3 gBig(N_NODES / 128, G4H / 128);
    gemm_nt<128, 128, 8, 8><<<gBig, 256>>>(pa2, wih0, pG, N_NODES, G4H, GNN_H,
                                           bih0, bhh0, nullptr, 0);
    dim3 gStep(BATCH / 64, G4H / 64);
    for (int t = 0; t < SEQ; t++) {
        gemm_nt<64, 64, 4, 4><<<gStep, 256>>>(ph, whh0, pg, BATCH, G4H, RNN_H,
                                              nullptr, nullptr,
                                              pG + (size_t)t * G4H, SEQ * G4H);
        lstm_pw<<<(BATCH * RNN_H) / 256, 256>>>(pg, ph, pc, pY, t);
    }

    // --- LSTM layer 1
    cudaMemsetAsync(ph, 0, BATCH * RNN_H * sizeof(float), 0);
    cudaMemsetAsync(pc, 0, BATCH * RNN_H * sizeof(float), 0);
    gemm_nt<128, 128, 8, 8><<<gBig, 256>>>(pY, wih1, pG, N_NODES, G4H, RNN_H,
                                           bih1, bhh1, nullptr, 0);
    for (int t = 0; t < SEQ; t++) {
        gemm_nt<64, 64, 4, 4><<<gStep, 256>>>(ph, whh1, pg, BATCH, G4H, RNN_H,
                                              nullptr, nullptr,
                                              pG + (size_t)t * G4H, SEQ * G4H);
        lstm_pw<<<(BATCH * RNN_H) / 256, 256>>>(pg, ph, pc, nullptr, t);
    }

    // --- FC head
    k_fc<<<(BATCH * OUT_DIM + 255) / 256, 256>>>(ph, fcw, fcb, out);
}